// round 3
// baseline (speedup 1.0000x reference)
#include <cuda_runtime.h>
#include <math.h>

#define HH 1024
#define WW 1024
#define NPIX (HH * WW)
#define COL_BLOCK 256
#define COL_GRID (NPIX / COL_BLOCK)   // 4096 blocks per image

// Scratch (no allocations allowed in kernel_launch)
__device__ unsigned char g_edges[2][NPIX];     // 2 MB
__device__ float         g_g2[2][NPIX];        // 8 MB
__device__ float         g_blockSums[2 * COL_GRID];

// ---------------------------------------------------------------------------
// Kernel 1: fused edge detection + per-row 1D distance (g2).
// One block per (row, image); 1024 threads = one per column.
// edges = seg - erode3x3(seg);   g = dist to nearest edge pixel in this row,
// with the reference's BIG=1e6 defaults when a side (or the whole row) is empty.
// ---------------------------------------------------------------------------
__global__ void __launch_bounds__(WW) edges_rowscan_kernel(
    const float* __restrict__ preds, const float* __restrict__ targets)
{
    const int i = blockIdx.x;       // row
    const int m = blockIdx.y;       // image: 0=preds, 1=targets
    const int j = threadIdx.x;      // column
    const float* __restrict__ seg = (m == 0) ? preds : targets;

    __shared__ unsigned char srow[WW];

    // ---- edges ----
    const float c = seg[i * WW + j];
    unsigned char e = 0;
    if (c != 0.0f) {
        bool eroded = (i > 0) && (i < HH - 1) && (j > 0) && (j < WW - 1);
        if (eroded) {
            #pragma unroll
            for (int di = -1; di <= 1; di++) {
                #pragma unroll
                for (int dj = -1; dj <= 1; dj++) {
                    if (seg[(i + di) * WW + (j + dj)] != 1.0f) eroded = false;
                }
            }
        }
        e = eroded ? 0 : 1;   // seg==1 here, so edges = 1 - eroded
    }
    srow[j] = e;
    g_edges[m][i * WW + j] = e;
    __syncthreads();

    // ---- nearest feature in row (exact, outward search in shared) ----
    float g;
    if (e) {
        g = 0.0f;
    } else {
        int d = 1;
        bool found = false;
        for (; d < WW; d++) {
            const int l = j - d, r = j + d;
            bool hit = false;
            if (l >= 0 && srow[l]) hit = true;
            if (r < WW && srow[r]) hit = true;
            if (hit) { found = true; break; }
            if (l < 0 && r >= WW) break;
        }
        if (found) {
            g = (float)d;   // integer distance, < 1e6 cap automatically
        } else {
            // replicate reference defaults exactly:
            // left = j + 1e6, right = 1e6 - j, g = min(left, right, 1e6)
            const float left  = (float)j + 1e6f;
            const float right = 1e6f - (float)j;
            g = fminf(fminf(left, right), 1e6f);
        }
    }
    g_g2[m][i * WW + j] = g * g;
}

// ---------------------------------------------------------------------------
// Kernel 2: column lower-envelope (exact, pruned) + masked accumulation.
// D2[i][j] = min_k g2[k][j] + (i-k)^2. Iterate delta outward; once
// delta^2 >= best no farther row can improve (g2 >= 0) -> exact early exit.
// Only computed where the OTHER image's edge mask is 1 (the weight).
// Deterministic block-level tree reduction into g_blockSums.
// ---------------------------------------------------------------------------
__global__ void __launch_bounds__(COL_BLOCK) colpass_kernel()
{
    const int p = blockIdx.x * COL_BLOCK + threadIdx.x;   // pixel index
    const int m = blockIdx.y;                             // image whose DT we take

    float contrib = 0.0f;
    if (g_edges[1 - m][p]) {                 // weight = other image's edges (0/1)
        const float* __restrict__ g2 = g_g2[m];
        float best = g2[p];
        for (int d = 1; ; d++) {
            const float dd = (float)(d * d);     // exact for d <= 1024
            if (dd >= best) break;               // provably cannot improve
            const int up = p - d * WW;
            const int dn = p + d * WW;
            if (up >= 0)   best = fminf(best, g2[up] + dd);
            if (dn < NPIX) best = fminf(best, g2[dn] + dd);
            if (up < 0 && dn >= NPIX) break;
        }
        contrib = sqrtf(best);
    }

    // deterministic in-block reduction: warp shuffles + fixed shared tree
    float v = contrib;
    #pragma unroll
    for (int o = 16; o > 0; o >>= 1) v += __shfl_down_sync(0xffffffffu, v, o);

    __shared__ float warpsum[COL_BLOCK / 32];
    if ((threadIdx.x & 31) == 0) warpsum[threadIdx.x >> 5] = v;
    __syncthreads();

    if (threadIdx.x < (COL_BLOCK / 32)) {
        float w = warpsum[threadIdx.x];
        #pragma unroll
        for (int o = (COL_BLOCK / 64); o > 0; o >>= 1)
            w += __shfl_down_sync(0xffu, w, o);
        if (threadIdx.x == 0)
            g_blockSums[m * COL_GRID + blockIdx.x] = w;
    }
}

// ---------------------------------------------------------------------------
// Kernel 3: deterministic final reduction + sigmoid.
// loss = (sum_pred_err + sum_target_err) / (2*N); out = sigmoid(loss)
// ---------------------------------------------------------------------------
__global__ void __launch_bounds__(1024) finalize_kernel(float* __restrict__ out)
{
    __shared__ float sh[1024];
    float s = 0.0f;
    for (int k = threadIdx.x; k < 2 * COL_GRID; k += 1024) s += g_blockSums[k];
    sh[threadIdx.x] = s;
    __syncthreads();
    #pragma unroll
    for (int stride = 512; stride > 0; stride >>= 1) {
        if (threadIdx.x < stride) sh[threadIdx.x] += sh[threadIdx.x + stride];
        __syncthreads();
    }
    if (threadIdx.x == 0) {
        const float loss = sh[0] / (2.0f * (float)NPIX);
        out[0] = 1.0f / (1.0f + expf(-loss));
    }
}

// ---------------------------------------------------------------------------
extern "C" void kernel_launch(void* const* d_in, const int* in_sizes, int n_in,
                              void* d_out, int out_size)
{
    const float* preds   = (const float*)d_in[0];
    const float* targets = (const float*)d_in[1];
    float* out = (float*)d_out;

    (void)in_sizes; (void)n_in; (void)out_size;

    dim3 gridA(HH, 2);
    edges_rowscan_kernel<<<gridA, WW>>>(preds, targets);

    dim3 gridB(COL_GRID, 2);
    colpass_kernel<<<gridB, COL_BLOCK>>>();

    finalize_kernel<<<1, 1024>>>(out);
}